// round 3
// baseline (speedup 1.0000x reference)
#include <cuda_runtime.h>

#define NPTS  40000
#define NMASK 30000
#define NINST 1024
#define NB    4
#define L0    2          // first layer used (L-4)
#define NL    4          // number of layers used
#define NLBL  41         // instance labels -1..39 -> index 0..40
#define NSEM  20
#define NBIN  (NB * NSEM)

// ---------------- scratch (device globals; no allocation allowed) ----------
__device__ int   g_sins[NINST];
__device__ int   g_sseg[NINST];
__device__ int   g_histAll[NB * NLBL];
__device__ int   g_histF[NB * NLBL];
__device__ int   g_histSem[NBIN];
__device__ int   g_histJ[NBIN * NLBL];
__device__ int   g_bstart[NB + 1];
__device__ int   g_binoff[NBIN];
__device__ __align__(16) int g_packed[NMASK];   // sem | ((ins+1)<<8) per fg point
__device__ int   g_list[NMASK];                 // j | ((ins+1)<<16), grouped by (b,sem)
__device__ float g_wrow[NINST];
__device__ float g_wg[NINST];
__device__ float g_cnt[NINST];
__device__ float g_inter[NL * NINST];
__device__ float g_p2[NL * NINST];
__device__ float g_bceS[NL * NINST];

// ---------------- K1: zero state, per-instance labels, batch ranges --------
__global__ void k_init(const int* __restrict__ fps32,
                       const int* __restrict__ instl,
                       const int* __restrict__ seml,
                       const int* __restrict__ bidx) {
    int t = threadIdx.x;   // blockDim = 1024
    for (int k = t; k < NB * NLBL; k += 1024) { g_histAll[k] = 0; g_histF[k] = 0; }
    for (int k = t; k < NBIN; k += 1024) g_histSem[k] = 0;
    for (int k = t; k < NBIN * NLBL; k += 1024) g_histJ[k] = 0;
    // zero per-row outputs (k_main only writes positive rows)
    g_wrow[t] = 0.f; g_wg[t] = 0.f; g_cnt[t] = 0.f;
    #pragma unroll
    for (int l = 0; l < NL; l++) {
        g_inter[l * NINST + t] = 0.f;
        g_p2[l * NINST + t]    = 0.f;
        g_bceS[l * NINST + t]  = 0.f;
    }
    {   // per-instance sampled labels.
        // Dtype sniff: if fps is int64 (LE), int32 lanes are [v0,0,v1,0,...]
        // (all values are small non-negative). 16 odd lanes all zero => int64.
        bool is64 = true;
        #pragma unroll
        for (int k = 0; k < 16; k++)
            if (fps32[2 * k + 1] != 0) { is64 = false; break; }
        int fi = is64 ? fps32[2 * t] : fps32[t];
        g_sins[t] = instl[fi];
        g_sseg[t] = seml[fi];
    }
    if (t <= NB) {
        if (t == 0)       g_bstart[0]  = 0;
        else if (t == NB) g_bstart[NB] = NMASK;
        else {            // lower bound of batch id t in sorted batch_idxs
            int lo = 0, hi = NMASK;
            while (lo < hi) { int mid = (lo + hi) >> 1; if (bidx[mid] < t) lo = mid + 1; else hi = mid; }
            g_bstart[t] = lo;
        }
    }
}

// ---------------- K2: histogram of instance labels over ALL points (den) ---
__global__ void k_histAll(const int* __restrict__ instl,
                          const int* __restrict__ offs) {
    __shared__ int sh[NB * NLBL];
    int t = threadIdx.x;
    for (int k = t; k < NB * NLBL; k += blockDim.x) sh[k] = 0;
    __syncthreads();
    int o1 = offs[1], o2 = offs[2], o3 = offs[3];
    for (int p = blockIdx.x * blockDim.x + t; p < NPTS; p += gridDim.x * blockDim.x) {
        int b = (p >= o1) + (p >= o2) + (p >= o3);
        int l = instl[p] + 1;
        atomicAdd(&sh[b * NLBL + l], 1);
    }
    __syncthreads();
    for (int k = t; k < NB * NLBL; k += blockDim.x)
        if (sh[k]) atomicAdd(&g_histAll[k], sh[k]);
}

// ---------------- K3: fg-point histograms + packed label array -------------
__global__ void k_histFg(const int* __restrict__ fg,
                         const int* __restrict__ instl,
                         const int* __restrict__ seml,
                         const int* __restrict__ bidx) {
    __shared__ int shF[NB * NLBL];
    __shared__ int shS[NBIN];
    __shared__ int shJ[NBIN * NLBL];
    int t = threadIdx.x;
    for (int k = t; k < NB * NLBL; k += blockDim.x) shF[k] = 0;
    for (int k = t; k < NBIN; k += blockDim.x) shS[k] = 0;
    for (int k = t; k < NBIN * NLBL; k += blockDim.x) shJ[k] = 0;
    __syncthreads();
    for (int j = blockIdx.x * blockDim.x + t; j < NMASK; j += gridDim.x * blockDim.x) {
        int fi  = fg[j];
        int ins = instl[fi];
        int sem = seml[fi];
        int b   = bidx[j];
        g_packed[j] = sem | ((ins + 1) << 8);
        atomicAdd(&shF[b * NLBL + ins + 1], 1);
        atomicAdd(&shS[b * NSEM + sem], 1);
        atomicAdd(&shJ[(b * NSEM + sem) * NLBL + ins + 1], 1);
    }
    __syncthreads();
    for (int k = t; k < NB * NLBL; k += blockDim.x) if (shF[k]) atomicAdd(&g_histF[k], shF[k]);
    for (int k = t; k < NBIN; k += blockDim.x) if (shS[k]) atomicAdd(&g_histSem[k], shS[k]);
    for (int k = t; k < NBIN * NLBL; k += blockDim.x) if (shJ[k]) atomicAdd(&g_histJ[k], shJ[k]);
}

// ---------------- K4: deterministic per-(batch,sem) compaction -------------
// One warp per bin. Output order within a bin is ascending j -> bit-stable.
__global__ void k_compact() {
    int w    = (blockIdx.x * blockDim.x + threadIdx.x) >> 5;
    int lane = threadIdx.x & 31;
    if (w >= NBIN) return;
    int b = w / NSEM, sem = w % NSEM;

    // exclusive prefix: sum of histSem bins before this one
    int off = 0;
    for (int k = lane; k < w; k += 32) off += g_histSem[k];
    #pragma unroll
    for (int o = 16; o > 0; o >>= 1) off += __shfl_down_sync(0xffffffffu, off, o);
    off = __shfl_sync(0xffffffffu, off, 0);
    if (lane == 0) g_binoff[w] = off;

    int jlo = g_bstart[b], jhi = g_bstart[b + 1];
    int base = off;
    for (int j0 = jlo; j0 < jhi; j0 += 32) {
        int j = j0 + lane;
        int pv = (j < jhi) ? g_packed[j] : -1;
        bool m = (j < jhi) && ((pv & 0xFF) == sem);
        unsigned bal = __ballot_sync(0xffffffffu, m);
        if (m) {
            int rank = __popc(bal & ((1u << lane) - 1));
            g_list[base + rank] = j | ((pv >> 8) << 16);
        }
        base += __popc(bal);
    }
}

// ---------------- K5 (main): sparse per-instance gather over 4 layers ------
__global__ void __launch_bounds__(128) k_main(const float* __restrict__ logits) {
    const int i = blockIdx.x;
    const int t = threadIdx.x;
    const int b = i >> 8;
    const int sins = g_sins[i];
    const int sseg = g_sseg[i];

    if (!(sins >= 0 && sseg >= 4)) return;
    {
        int num = g_histF[b * NLBL + sins + 1];
        int den = g_histAll[b * NLBL + sins + 1];
        float cover = __fdiv_rn((float)num, (float)den);  // RN: bit-match jnp; den=0 -> NaN -> not positive
        if (!(cover >= 0.3f)) return;
    }

    const int bin = b * NSEM + sseg;
    const int cnt = g_histSem[bin];
    const int off = g_binoff[bin];
    if (t == 0) {
        g_wrow[i] = (float)cnt;
        g_wg[i]   = (float)g_histJ[bin * NLBL + sins + 1];
        g_cnt[i]  = (cnt > 0) ? 1.f : 0.f;
    }

    const size_t lstride = (size_t)NINST * NMASK;
    const float* row = logits + (size_t)L0 * lstride + (size_t)i * NMASK;
    const int key = sins + 1;

    float acc[12];                    // [0..3]=inter, [4..7]=p2, [8..11]=bce
    #pragma unroll
    for (int k = 0; k < 12; k++) acc[k] = 0.f;

    for (int e = t; e < cnt; e += 128) {
        int ent = g_list[off + e];
        int jj  = ent & 0xFFFF;
        float gtf = ((ent >> 16) == key) ? 1.f : 0.f;
        const float* pj = row + jj;
        float xs[NL];
        xs[0] = __ldg(pj);
        xs[1] = __ldg(pj + lstride);
        xs[2] = __ldg(pj + 2 * lstride);
        xs[3] = __ldg(pj + 3 * lstride);
        #pragma unroll
        for (int l = 0; l < NL; l++) {
            float x  = xs[l];
            float ax = fabsf(x);
            float e1 = __expf(-ax);
            float d1 = 1.0f + e1;
            float inv = __fdividef(1.0f, d1);
            float s  = (x >= 0.f) ? inv : e1 * inv;       // sigmoid(x)
            float sp = fmaxf(x, 0.f) + __logf(d1);        // softplus(x)
            acc[l]     += s * gtf;                        // inter
            acc[4 + l] += s * s;                          // pred^2
            acc[8 + l] += sp - gtf * x;                   // bce
        }
    }

    // block reduction: 4 warps x 12 values
    #pragma unroll
    for (int k = 0; k < 12; k++) {
        #pragma unroll
        for (int o = 16; o > 0; o >>= 1)
            acc[k] += __shfl_down_sync(0xffffffffu, acc[k], o);
    }
    __shared__ float red[4][12];
    int wid = t >> 5, lane = t & 31;
    if (lane == 0) {
        #pragma unroll
        for (int k = 0; k < 12; k++) red[wid][k] = acc[k];
    }
    __syncthreads();
    if (wid == 0 && lane == 0) {
        #pragma unroll
        for (int l = 0; l < NL; l++) {
            g_inter[l * NINST + i] = red[0][l]     + red[1][l]     + red[2][l]     + red[3][l];
            g_p2[l * NINST + i]    = red[0][4 + l] + red[1][4 + l] + red[2][4 + l] + red[3][4 + l];
            g_bceS[l * NINST + i]  = red[0][8 + l] + red[1][8 + l] + red[2][8 + l] + red[3][8 + l];
        }
    }
}

// ---------------- K6: final reduction -> scalar loss -----------------------
__global__ void k_final(float* __restrict__ out) {
    int t = threadIdx.x;    // blockDim = 1024 == NINST
    float v[10];
    float cnt = g_cnt[t];
    float wg  = g_wg[t];
    v[0] = cnt;
    v[1] = g_wrow[t];
    #pragma unroll
    for (int l = 0; l < NL; l++) {
        v[2 + l] = g_bceS[l * NINST + t];
        float un = g_p2[l * NINST + t] + wg + 1e-5f;
        v[6 + l] = cnt * (1.0f - 2.0f * g_inter[l * NINST + t] / un);
    }
    #pragma unroll
    for (int k = 0; k < 10; k++) {
        #pragma unroll
        for (int o = 16; o > 0; o >>= 1)
            v[k] += __shfl_down_sync(0xffffffffu, v[k], o);
    }
    __shared__ float red[32][10];
    int wid = t >> 5, lane = t & 31;
    if (lane == 0) {
        #pragma unroll
        for (int k = 0; k < 10; k++) red[wid][k] = v[k];
    }
    __syncthreads();
    if (wid == 0) {
        float r[10];
        #pragma unroll
        for (int k = 0; k < 10; k++) r[k] = red[lane][k];
        #pragma unroll
        for (int k = 0; k < 10; k++) {
            #pragma unroll
            for (int o = 16; o > 0; o >>= 1)
                r[k] += __shfl_down_sync(0xffffffffu, r[k], o);
        }
        if (lane == 0) {
            float csum = r[0] + 1e-6f;
            float wsum = r[1] + 1e-6f;
            float loss = 0.f;
            #pragma unroll
            for (int l = 0; l < NL; l++)
                loss += r[2 + l] / wsum + r[6 + l] / csum;
            out[0] = loss;
        }
    }
}

// ---------------- entry ----------------------------------------------------
extern "C" void kernel_launch(void* const* d_in, const int* in_sizes, int n_in,
                              void* d_out, int out_size) {
    const float* logits = (const float*)d_in[0];
    const int*   seml   = (const int*)d_in[1];
    const int*   instl  = (const int*)d_in[2];
    const int*   fg     = (const int*)d_in[3];
    const int*   bidx   = (const int*)d_in[4];
    const int*   offs   = (const int*)d_in[5];
    const int*   fps    = (const int*)d_in[6];   // int32 (JAX x64 disabled); sniffed for int64 in k_init
    (void)in_sizes; (void)n_in; (void)out_size;

    k_init<<<1, 1024>>>(fps, instl, seml, bidx);
    k_histAll<<<80, 512>>>(instl, offs);
    k_histFg<<<120, 256>>>(fg, instl, seml, bidx);
    k_compact<<<10, 256>>>();
    k_main<<<NINST, 128>>>(logits);
    k_final<<<1, 1024>>>((float*)d_out);
}

// round 7
// speedup vs baseline: 3.4923x; 3.4923x over previous
#include <cuda_runtime.h>

#define NPTS  40000
#define NMASK 30000
#define NINST 1024
#define NB    4
#define L0    2          // first layer used (L-4)
#define NL    4          // number of layers used
#define NLBL  41         // instance labels -1..39 -> index 0..40
#define NSEM  20
#define NBIN  (NB * NSEM)
#define NCHUNK 30        // ceil(NMASK / 1024)

// ---------------- scratch (device globals; no allocation allowed) ----------
__device__ int   g_sins[NINST];
__device__ int   g_sseg[NINST];
__device__ int   g_histAll[NB * NLBL];
__device__ int   g_histF[NB * NLBL];
__device__ int   g_histSem[NBIN];
__device__ int   g_histJ[NBIN * NLBL];
__device__ int   g_binoff[NBIN];
__device__ int   g_chunkCnt[NCHUNK][NBIN];      // counts -> (after k_scan) global base offsets
__device__ __align__(16) int g_packed[NMASK];   // sem | ((ins+1)<<8) per fg point
__device__ int   g_list[NMASK];                 // j | ((ins+1)<<16), grouped by (b,sem), ascending j
__device__ float g_wrow[NINST];
__device__ float g_wg[NINST];
__device__ float g_cnt[NINST];
__device__ float g_inter[NL * NINST];
__device__ float g_p2[NL * NINST];
__device__ float g_bceS[NL * NINST];

// ---------------- K1: zero state, per-instance labels ----------------------
__global__ void k_init(const int* __restrict__ fps32,
                       const int* __restrict__ instl,
                       const int* __restrict__ seml) {
    int t = threadIdx.x;   // blockDim = 1024
    for (int k = t; k < NB * NLBL; k += 1024) { g_histAll[k] = 0; g_histF[k] = 0; }
    for (int k = t; k < NBIN; k += 1024) g_histSem[k] = 0;
    for (int k = t; k < NBIN * NLBL; k += 1024) g_histJ[k] = 0;
    // zero per-row outputs (k_main only writes positive rows)
    g_wrow[t] = 0.f; g_wg[t] = 0.f; g_cnt[t] = 0.f;
    #pragma unroll
    for (int l = 0; l < NL; l++) {
        g_inter[l * NINST + t] = 0.f;
        g_p2[l * NINST + t]    = 0.f;
        g_bceS[l * NINST + t]  = 0.f;
    }
    {   // per-instance sampled labels.
        // Dtype sniff: int64 (LE) buffer looks like [v0,0,v1,0,...] in int32 lanes.
        bool is64 = true;
        #pragma unroll
        for (int k = 0; k < 16; k++)
            if (fps32[2 * k + 1] != 0) { is64 = false; break; }
        int fi = is64 ? fps32[2 * t] : fps32[t];
        g_sins[t] = instl[fi];
        g_sseg[t] = seml[fi];
    }
}

// ---------------- K2: all histograms + packed labels + chunk counts --------
// grid = NCHUNK blocks x 1024. Block bid owns fg points [bid*1024, bid*1024+1024).
__global__ void __launch_bounds__(1024) k_hist(const int* __restrict__ fg,
                                               const int* __restrict__ instl,
                                               const int* __restrict__ seml,
                                               const int* __restrict__ bidx,
                                               const int* __restrict__ offs) {
    __shared__ int shF[NB * NLBL];
    __shared__ int shS[NBIN];
    __shared__ int shJ[NBIN * NLBL];
    __shared__ int shAll[NB * NLBL];
    __shared__ int shC[NBIN];
    int t = threadIdx.x;
    for (int k = t; k < NB * NLBL; k += 1024) { shF[k] = 0; shAll[k] = 0; }
    for (int k = t; k < NBIN; k += 1024) { shS[k] = 0; shC[k] = 0; }
    for (int k = t; k < NBIN * NLBL; k += 1024) shJ[k] = 0;
    __syncthreads();

    // fg-point part: one thread per j in this chunk
    int j = blockIdx.x * 1024 + t;
    if (j < NMASK) {
        int fi  = fg[j];
        int ins = instl[fi];
        int sem = seml[fi];
        int b   = bidx[j];
        int bin = b * NSEM + sem;
        g_packed[j] = sem | ((ins + 1) << 8);
        atomicAdd(&shF[b * NLBL + ins + 1], 1);
        atomicAdd(&shS[bin], 1);
        atomicAdd(&shC[bin], 1);
        atomicAdd(&shJ[bin * NLBL + ins + 1], 1);
    }

    // all-points part (den histogram): grid-stride over NPTS
    int o1 = offs[1], o2 = offs[2], o3 = offs[3];
    for (int p = blockIdx.x * 1024 + t; p < NPTS; p += NCHUNK * 1024) {
        int b = (p >= o1) + (p >= o2) + (p >= o3);
        atomicAdd(&shAll[b * NLBL + instl[p] + 1], 1);
    }
    __syncthreads();

    for (int k = t; k < NB * NLBL; k += 1024) {
        if (shF[k])   atomicAdd(&g_histF[k], shF[k]);
        if (shAll[k]) atomicAdd(&g_histAll[k], shAll[k]);
    }
    for (int k = t; k < NBIN; k += 1024) {
        if (shS[k]) atomicAdd(&g_histSem[k], shS[k]);
        g_chunkCnt[blockIdx.x][k] = shC[k];       // exact, no atomic needed
    }
    for (int k = t; k < NBIN * NLBL; k += 1024)
        if (shJ[k]) atomicAdd(&g_histJ[k], shJ[k]);
}

// ---------------- K3: turn chunk counts into global base offsets -----------
// single block, 128 threads. chunkCnt[c][bin] <- binoff[bin] + prefix_c(cnt).
__global__ void k_scan() {
    __shared__ int shTot[NBIN];
    __shared__ int shOff[NBIN];
    int t = threadIdx.x;
    if (t < NBIN) {
        int run = 0;
        #pragma unroll
        for (int c = 0; c < NCHUNK; c++) {
            int v = g_chunkCnt[c][t];
            g_chunkCnt[c][t] = run;               // chunk-local exclusive prefix
            run += v;
        }
        shTot[t] = run;
    }
    __syncthreads();
    if (t == 0) {
        int off = 0;
        for (int k = 0; k < NBIN; k++) { shOff[k] = off; off += shTot[k]; }
    }
    __syncthreads();
    if (t < NBIN) {
        g_binoff[t] = shOff[t];
        #pragma unroll
        for (int c = 0; c < NCHUNK; c++) g_chunkCnt[c][t] += shOff[t];
    }
}

// ---------------- K4: deterministic parallel scatter ------------------------
// grid = NCHUNK x 1024. Rank within bin = ascending j (chunk, warp, lane order).
__global__ void __launch_bounds__(1024) k_scatter(const int* __restrict__ bidx) {
    __shared__ int wcnt[32][NBIN];
    int t = threadIdx.x;
    int warp = t >> 5, lane = t & 31;
    for (int k = t; k < 32 * NBIN; k += 1024) ((int*)wcnt)[k] = 0;
    __syncthreads();

    int j = blockIdx.x * 1024 + t;
    bool valid = (j < NMASK);
    int pv = 0, bin = NBIN;
    if (valid) {
        pv  = g_packed[j];
        bin = bidx[j] * NSEM + (pv & 0xFF);
    }
    unsigned grp = __match_any_sync(0xffffffffu, bin);
    int wrank = __popc(grp & ((1u << lane) - 1));
    if (valid && wrank == 0) wcnt[warp][bin] = __popc(grp);   // group leader
    __syncthreads();
    if (valid) {
        int base = g_chunkCnt[blockIdx.x][bin];
        int sum = 0;
        for (int w = 0; w < warp; w++) sum += wcnt[w][bin];
        g_list[base + sum + wrank] = j | ((pv >> 8) << 16);
    }
}

// ---------------- K5 (main): sparse gather, one block per (layer, instance) -
__global__ void __launch_bounds__(128) k_main(const float* __restrict__ logits) {
    const int i = blockIdx.x & (NINST - 1);
    const int l = blockIdx.x >> 10;          // 0..NL-1
    const int t = threadIdx.x;
    const int b = i >> 8;
    const int sins = g_sins[i];
    const int sseg = g_sseg[i];

    if (!(sins >= 0 && sseg >= 4)) return;
    {
        int num = g_histF[b * NLBL + sins + 1];
        int den = g_histAll[b * NLBL + sins + 1];
        float cover = __fdiv_rn((float)num, (float)den);  // RN: bit-match jnp; den=0 -> NaN -> not positive
        if (!(cover >= 0.3f)) return;
    }

    const int bin = b * NSEM + sseg;
    const int cnt = g_histSem[bin];
    const int off = g_binoff[bin];
    if (t == 0 && l == 0) {
        g_wrow[i] = (float)cnt;
        g_wg[i]   = (float)g_histJ[bin * NLBL + sins + 1];
        g_cnt[i]  = (cnt > 0) ? 1.f : 0.f;
    }

    const size_t lstride = (size_t)NINST * NMASK;
    const float* row = logits + (size_t)(L0 + l) * lstride + (size_t)i * NMASK;
    const int key = sins + 1;

    float aI = 0.f, aP = 0.f, aB = 0.f;      // inter, pred^2, bce
    for (int e = t; e < cnt; e += 128) {
        int ent = g_list[off + e];
        int jj  = ent & 0xFFFF;
        float gtf = ((ent >> 16) == key) ? 1.f : 0.f;
        float x  = __ldg(row + jj);
        float ax = fabsf(x);
        float e1 = __expf(-ax);
        float d1 = 1.0f + e1;
        float inv = __fdividef(1.0f, d1);
        float s  = (x >= 0.f) ? inv : e1 * inv;       // sigmoid(x)
        float sp = fmaxf(x, 0.f) + __logf(d1);        // softplus(x)
        aI += s * gtf;
        aP += s * s;
        aB += sp - gtf * x;
    }

    // block reduction: 4 warps x 3 values
    #pragma unroll
    for (int o = 16; o > 0; o >>= 1) {
        aI += __shfl_down_sync(0xffffffffu, aI, o);
        aP += __shfl_down_sync(0xffffffffu, aP, o);
        aB += __shfl_down_sync(0xffffffffu, aB, o);
    }
    __shared__ float red[4][3];
    int wid = t >> 5, lane = t & 31;
    if (lane == 0) { red[wid][0] = aI; red[wid][1] = aP; red[wid][2] = aB; }
    __syncthreads();
    if (wid == 0 && lane == 0) {
        g_inter[l * NINST + i] = red[0][0] + red[1][0] + red[2][0] + red[3][0];
        g_p2[l * NINST + i]    = red[0][1] + red[1][1] + red[2][1] + red[3][1];
        g_bceS[l * NINST + i]  = red[0][2] + red[1][2] + red[2][2] + red[3][2];
    }
}

// ---------------- K6: final reduction -> scalar loss -----------------------
__global__ void k_final(float* __restrict__ out) {
    int t = threadIdx.x;    // blockDim = 1024 == NINST
    float v[10];
    float cnt = g_cnt[t];
    float wg  = g_wg[t];
    v[0] = cnt;
    v[1] = g_wrow[t];
    #pragma unroll
    for (int l = 0; l < NL; l++) {
        v[2 + l] = g_bceS[l * NINST + t];
        float un = g_p2[l * NINST + t] + wg + 1e-5f;
        v[6 + l] = cnt * (1.0f - 2.0f * g_inter[l * NINST + t] / un);
    }
    #pragma unroll
    for (int k = 0; k < 10; k++) {
        #pragma unroll
        for (int o = 16; o > 0; o >>= 1)
            v[k] += __shfl_down_sync(0xffffffffu, v[k], o);
    }
    __shared__ float red[32][10];
    int wid = t >> 5, lane = t & 31;
    if (lane == 0) {
        #pragma unroll
        for (int k = 0; k < 10; k++) red[wid][k] = v[k];
    }
    __syncthreads();
    if (wid == 0) {
        float r[10];
        #pragma unroll
        for (int k = 0; k < 10; k++) r[k] = red[lane][k];
        #pragma unroll
        for (int k = 0; k < 10; k++) {
            #pragma unroll
            for (int o = 16; o > 0; o >>= 1)
                r[k] += __shfl_down_sync(0xffffffffu, r[k], o);
        }
        if (lane == 0) {
            float csum = r[0] + 1e-6f;
            float wsum = r[1] + 1e-6f;
            float loss = 0.f;
            #pragma unroll
            for (int l = 0; l < NL; l++)
                loss += r[2 + l] / wsum + r[6 + l] / csum;
            out[0] = loss;
        }
    }
}

// ---------------- entry ----------------------------------------------------
extern "C" void kernel_launch(void* const* d_in, const int* in_sizes, int n_in,
                              void* d_out, int out_size) {
    const float* logits = (const float*)d_in[0];
    const int*   seml   = (const int*)d_in[1];
    const int*   instl  = (const int*)d_in[2];
    const int*   fg     = (const int*)d_in[3];
    const int*   bidx   = (const int*)d_in[4];
    const int*   offs   = (const int*)d_in[5];
    const int*   fps    = (const int*)d_in[6];   // int32 (sniffed for int64 in k_init)
    (void)in_sizes; (void)n_in; (void)out_size;

    k_init<<<1, 1024>>>(fps, instl, seml);
    k_hist<<<NCHUNK, 1024>>>(fg, instl, seml, bidx, offs);
    k_scan<<<1, 128>>>();
    k_scatter<<<NCHUNK, 1024>>>(bidx);
    k_main<<<NINST * NL, 128>>>(logits);
    k_final<<<1, 1024>>>((float*)d_out);
}

// round 9
// speedup vs baseline: 3.7348x; 1.0694x over previous
#include <cuda_runtime.h>

#define NPTS  40000
#define NMASK 30000
#define NINST 1024
#define NB    4
#define L0    2          // first layer used (L-4)
#define NL    4          // number of layers used
#define NLBL  41         // instance labels -1..39 -> index 0..40
#define NSEM  20
#define NBIN  (NB * NSEM)
#define NCHUNK 30        // ceil(NMASK / 1024)

// ---------------- scratch (device globals; no allocation allowed) ----------
// Invariant: all accumulated / conditionally-written buffers are ZERO on entry
// to kernel_launch. Initially true (module load); k_final restores it at exit.
__device__ int   g_sins[NINST];
__device__ int   g_sseg[NINST];
__device__ int   g_histAll[NB * NLBL];
__device__ int   g_histF[NB * NLBL];
__device__ int   g_histSem[NBIN];
__device__ int   g_histJ[NBIN * NLBL];
__device__ int   g_binoff[NBIN];
__device__ int   g_chunkCnt[NCHUNK][NBIN];      // fully rewritten by k_hist each call
__device__ __align__(16) int g_packed[NMASK];   // sem | ((ins+1)<<8) per fg point
__device__ int   g_list[NMASK];                 // j | ((ins+1)<<16), grouped by (b,sem), ascending j
__device__ float g_wrow[NINST];
__device__ float g_wg[NINST];
__device__ float g_cnt[NINST];
__device__ float g_inter[NL * NINST];
__device__ float g_p2[NL * NINST];
__device__ float g_bceS[NL * NINST];

// ---------------- K1: all histograms + packed labels + chunk counts --------
// grid = NCHUNK blocks x 1024. Block bid owns fg points [bid*1024, bid*1024+1024).
// Block 0 additionally loads the per-instance sampled labels.
__global__ void __launch_bounds__(1024) k_hist(const int* __restrict__ fg,
                                               const int* __restrict__ instl,
                                               const int* __restrict__ seml,
                                               const int* __restrict__ bidx,
                                               const int* __restrict__ offs,
                                               const int* __restrict__ fps32) {
    __shared__ int shF[NB * NLBL];
    __shared__ int shS[NBIN];
    __shared__ int shJ[NBIN * NLBL];
    __shared__ int shAll[NB * NLBL];
    int t = threadIdx.x;
    for (int k = t; k < NB * NLBL; k += 1024) { shF[k] = 0; shAll[k] = 0; }
    for (int k = t; k < NBIN; k += 1024) shS[k] = 0;
    for (int k = t; k < NBIN * NLBL; k += 1024) shJ[k] = 0;
    __syncthreads();

    if (blockIdx.x == 0) {
        // per-instance sampled labels; dtype sniff: int64 (LE) buffer looks
        // like [v0,0,v1,0,...] in int32 lanes (values are small non-negative).
        bool is64 = true;
        #pragma unroll
        for (int k = 0; k < 16; k++)
            if (fps32[2 * k + 1] != 0) { is64 = false; break; }
        int fi = is64 ? fps32[2 * t] : fps32[t];
        g_sins[t] = instl[fi];
        g_sseg[t] = seml[fi];
    }

    // fg-point part: one thread per j in this chunk
    int j = blockIdx.x * 1024 + t;
    if (j < NMASK) {
        int fi  = fg[j];
        int ins = instl[fi];
        int sem = seml[fi];
        int b   = bidx[j];
        int bin = b * NSEM + sem;
        g_packed[j] = sem | ((ins + 1) << 8);
        atomicAdd(&shF[b * NLBL + ins + 1], 1);
        atomicAdd(&shS[bin], 1);
        atomicAdd(&shJ[bin * NLBL + ins + 1], 1);
    }

    // all-points part (den histogram): grid-stride over NPTS
    int o1 = offs[1], o2 = offs[2], o3 = offs[3];
    for (int p = blockIdx.x * 1024 + t; p < NPTS; p += NCHUNK * 1024) {
        int b = (p >= o1) + (p >= o2) + (p >= o3);
        atomicAdd(&shAll[b * NLBL + instl[p] + 1], 1);
    }
    __syncthreads();

    for (int k = t; k < NB * NLBL; k += 1024) {
        if (shF[k])   atomicAdd(&g_histF[k], shF[k]);
        if (shAll[k]) atomicAdd(&g_histAll[k], shAll[k]);
    }
    for (int k = t; k < NBIN; k += 1024) {
        if (shS[k]) atomicAdd(&g_histSem[k], shS[k]);
        g_chunkCnt[blockIdx.x][k] = shS[k];       // exact per-chunk count
    }
    for (int k = t; k < NBIN * NLBL; k += 1024)
        if (shJ[k]) atomicAdd(&g_histJ[k], shJ[k]);
}

// ---------------- K2: scatter with fused offset computation ----------------
// grid = NCHUNK x 1024. Each block recomputes its own chunk base offsets from
// g_chunkCnt (redundant, L2-hit). Rank within bin = ascending j; bit-stable.
__global__ void __launch_bounds__(1024) k_scatter(const int* __restrict__ bidx) {
    __shared__ int wcnt[32][NBIN];
    __shared__ int sTot[NBIN];
    __shared__ int sBase[NBIN];   // global base offset of this chunk, per bin
    int t = threadIdx.x;
    int warp = t >> 5, lane = t & 31;
    for (int k = t; k < 32 * NBIN; k += 1024) ((int*)wcnt)[k] = 0;

    // phase A: per-bin grand totals + prefix over chunks before this block
    if (t < NBIN) {
        int tot = 0, pre = 0;
        #pragma unroll
        for (int c = 0; c < NCHUNK; c++) {
            int v = g_chunkCnt[c][t];
            pre += (c < (int)blockIdx.x) ? v : 0;
            tot += v;
        }
        sTot[t] = tot;
        sBase[t] = pre;
    }
    __syncthreads();
    if (t == 0) {
        int off = 0;
        #pragma unroll 4
        for (int k = 0; k < NBIN; k++) {
            sBase[k] += off;
            if (blockIdx.x == 0) g_binoff[k] = off;   // publish for k_main
            off += sTot[k];
        }
    }

    // phase B: per-warp group counts
    int j = blockIdx.x * 1024 + t;
    bool valid = (j < NMASK);
    int pv = 0, bin = NBIN;
    if (valid) {
        pv  = g_packed[j];
        bin = bidx[j] * NSEM + (pv & 0xFF);
    }
    unsigned grp = __match_any_sync(0xffffffffu, bin);
    int wrank = __popc(grp & ((1u << lane) - 1));
    if (valid && wrank == 0) wcnt[warp][bin] = __popc(grp);   // group leader
    __syncthreads();

    // phase C: bin-parallel exclusive scan across the 32 warps
    if (t < NBIN) {
        int run = 0;
        #pragma unroll
        for (int w = 0; w < 32; w++) {
            int v = wcnt[w][t];
            wcnt[w][t] = run;
            run += v;
        }
    }
    __syncthreads();

    if (valid)
        g_list[sBase[bin] + wcnt[warp][bin] + wrank] = j | ((pv >> 8) << 16);
}

// ---------------- K3 (main): sparse gather, one block per (layer, instance) -
__global__ void __launch_bounds__(128) k_main(const float* __restrict__ logits) {
    const int i = blockIdx.x & (NINST - 1);
    const int l = blockIdx.x >> 10;          // 0..NL-1
    const int t = threadIdx.x;
    const int b = i >> 8;
    const int sins = g_sins[i];
    const int sseg = g_sseg[i];

    if (!(sins >= 0 && sseg >= 4)) return;
    {
        int num = g_histF[b * NLBL + sins + 1];
        int den = g_histAll[b * NLBL + sins + 1];
        float cover = __fdiv_rn((float)num, (float)den);  // RN: bit-match jnp; den=0 -> NaN -> not positive
        if (!(cover >= 0.3f)) return;
    }

    const int bin = b * NSEM + sseg;
    const int cnt = g_histSem[bin];
    const int off = g_binoff[bin];
    if (t == 0 && l == 0) {
        g_wrow[i] = (float)cnt;
        g_wg[i]   = (float)g_histJ[bin * NLBL + sins + 1];
        g_cnt[i]  = (cnt > 0) ? 1.f : 0.f;
    }

    const size_t lstride = (size_t)NINST * NMASK;
    const float* row = logits + (size_t)(L0 + l) * lstride + (size_t)i * NMASK;
    const int key = sins + 1;

    float aI = 0.f, aP = 0.f, aB = 0.f;      // inter, pred^2, bce
    for (int e = t; e < cnt; e += 128) {
        int ent = g_list[off + e];
        int jj  = ent & 0xFFFF;
        float gtf = ((ent >> 16) == key) ? 1.f : 0.f;
        float x  = __ldg(row + jj);
        float ax = fabsf(x);
        float e1 = __expf(-ax);
        float d1 = 1.0f + e1;
        float inv = __fdividef(1.0f, d1);
        float s  = (x >= 0.f) ? inv : e1 * inv;       // sigmoid(x)
        float sp = fmaxf(x, 0.f) + __logf(d1);        // softplus(x)
        aI += s * gtf;
        aP += s * s;
        aB += sp - gtf * x;
    }

    // block reduction: 4 warps x 3 values
    #pragma unroll
    for (int o = 16; o > 0; o >>= 1) {
        aI += __shfl_down_sync(0xffffffffu, aI, o);
        aP += __shfl_down_sync(0xffffffffu, aP, o);
        aB += __shfl_down_sync(0xffffffffu, aB, o);
    }
    __shared__ float red[4][3];
    int wid = t >> 5, lane = t & 31;
    if (lane == 0) { red[wid][0] = aI; red[wid][1] = aP; red[wid][2] = aB; }
    __syncthreads();
    if (wid == 0 && lane == 0) {
        g_inter[l * NINST + i] = red[0][0] + red[1][0] + red[2][0] + red[3][0];
        g_p2[l * NINST + i]    = red[0][1] + red[1][1] + red[2][1] + red[3][1];
        g_bceS[l * NINST + i]  = red[0][2] + red[1][2] + red[2][2] + red[3][2];
    }
}

// ---------------- K4: final reduction -> scalar loss + state re-zero -------
__global__ void k_final(float* __restrict__ out) {
    int t = threadIdx.x;    // blockDim = 1024 == NINST
    float v[10];
    float cnt = g_cnt[t];
    float wg  = g_wg[t];
    v[0] = cnt;
    v[1] = g_wrow[t];
    #pragma unroll
    for (int l = 0; l < NL; l++) {
        v[2 + l] = g_bceS[l * NINST + t];
        float un = g_p2[l * NINST + t] + wg + 1e-5f;
        v[6 + l] = cnt * (1.0f - 2.0f * g_inter[l * NINST + t] / un);
    }

    // restore the zero-on-entry invariant for the next call
    g_wrow[t] = 0.f; g_wg[t] = 0.f; g_cnt[t] = 0.f;
    #pragma unroll
    for (int l = 0; l < NL; l++) {
        g_inter[l * NINST + t] = 0.f;
        g_p2[l * NINST + t]    = 0.f;
        g_bceS[l * NINST + t]  = 0.f;
    }
    for (int k = t; k < NB * NLBL; k += 1024) { g_histAll[k] = 0; g_histF[k] = 0; }
    for (int k = t; k < NBIN; k += 1024) g_histSem[k] = 0;
    for (int k = t; k < NBIN * NLBL; k += 1024) g_histJ[k] = 0;

    #pragma unroll
    for (int k = 0; k < 10; k++) {
        #pragma unroll
        for (int o = 16; o > 0; o >>= 1)
            v[k] += __shfl_down_sync(0xffffffffu, v[k], o);
    }
    __shared__ float red[32][10];
    int wid = t >> 5, lane = t & 31;
    if (lane == 0) {
        #pragma unroll
        for (int k = 0; k < 10; k++) red[wid][k] = v[k];
    }
    __syncthreads();
    if (wid == 0) {
        float r[10];
        #pragma unroll
        for (int k = 0; k < 10; k++) r[k] = red[lane][k];
        #pragma unroll
        for (int k = 0; k < 10; k++) {
            #pragma unroll
            for (int o = 16; o > 0; o >>= 1)
                r[k] += __shfl_down_sync(0xffffffffu, r[k], o);
        }
        if (lane == 0) {
            float csum = r[0] + 1e-6f;
            float wsum = r[1] + 1e-6f;
            float loss = 0.f;
            #pragma unroll
            for (int l = 0; l < NL; l++)
                loss += r[2 + l] / wsum + r[6 + l] / csum;
            out[0] = loss;
        }
    }
}

// ---------------- entry ----------------------------------------------------
extern "C" void kernel_launch(void* const* d_in, const int* in_sizes, int n_in,
                              void* d_out, int out_size) {
    const float* logits = (const float*)d_in[0];
    const int*   seml   = (const int*)d_in[1];
    const int*   instl  = (const int*)d_in[2];
    const int*   fg     = (const int*)d_in[3];
    const int*   bidx   = (const int*)d_in[4];
    const int*   offs   = (const int*)d_in[5];
    const int*   fps    = (const int*)d_in[6];   // int32 (sniffed for int64 in k_hist)
    (void)in_sizes; (void)n_in; (void)out_size;

    k_hist<<<NCHUNK, 1024>>>(fg, instl, seml, bidx, offs, fps);
    k_scatter<<<NCHUNK, 1024>>>(bidx);
    k_main<<<NINST * NL, 128>>>(logits);
    k_final<<<1, 1024>>>((float*)d_out);
}